// round 4
// baseline (speedup 1.0000x reference)
#include <cuda_runtime.h>
#include <cuda_bf16.h>
#include <cstdint>
#include <cstddef>

// Block-diagonal batched GEMM via bf16 HMMA (mma.sync) with hi/lo split.
// Round 4: preconverted bf16 x (hi/lo) + cp.async double-buffered mainloop.
//   out[start_g + r, c] = sum_h M_g[r,h] * x[start_g + h, c],  c in [0,10752)

#define NGROUPS 15
#define NCOLS   10752
#define NTILES  37
#define XROWS   2048
#define XROWS_PAD 2112   // +64 guard rows for last group's k-padding reads

__constant__ int c_g[NGROUPS]     = {64,128,256,96,160,224,192,288,320,112,80,48,32,16,32};
__constant__ int c_start[NGROUPS] = {0,64,192,448,544,704,928,1120,1408,1728,1840,1920,1968,2000,2016};
__constant__ int c_kpad[NGROUPS]  = {64,128,256,128,192,256,192,320,320,128,128,64,64,64,64};
__constant__ int c_aoff[NGROUPS]  = {0,4096,20480,86016,98304,129024,186368,223232,315392,417792,432128,442368,445440,447488,448512};
__constant__ int c_tileg[NTILES]  = {0, 1,1, 2,2,2,2, 3,3, 4,4,4, 5,5,5,5, 6,6,6,
                                     7,7,7,7,7, 8,8,8,8,8, 9,9, 10,10, 11, 12, 13, 14};
__constant__ int c_tiler[NTILES]  = {0, 0,64, 0,64,128,192, 0,64, 0,64,128, 0,64,128,192, 0,64,128,
                                     0,64,128,192,256, 0,64,128,192,256, 0,64, 0,64, 0, 0, 0, 0};

// Preconverted operands (device globals = sanctioned scratch; zero-initialized).
__device__ __nv_bfloat16 g_Ah[450560];
__device__ __nv_bfloat16 g_Al[450560];
__device__ __nv_bfloat16 g_Xh[XROWS_PAD * NCOLS];
__device__ __nv_bfloat16 g_Xl[XROWS_PAD * NCOLS];

struct MatPtrs { const float* p[NGROUPS]; };

// ---------------- PTX helpers (compute_103-legal) ----------------
__device__ __forceinline__ uint32_t smem_u32(const void* p) {
    uint32_t a;
    asm("{ .reg .u64 t; cvta.to.shared.u64 t, %1; cvt.u32.u64 %0, t; }" : "=r"(a) : "l"(p));
    return a;
}
__device__ __forceinline__ void cp16(uint32_t dst, const void* src) {
    asm volatile("cp.async.cg.shared.global [%0], [%1], 16;" :: "r"(dst), "l"(src));
}
#define CP_COMMIT() asm volatile("cp.async.commit_group;" ::: "memory")
#define CP_WAIT1()  asm volatile("cp.async.wait_group 1;" ::: "memory")

__device__ __forceinline__ void ldsm_x4(uint32_t* r, uint32_t addr) {
    asm volatile("ldmatrix.sync.aligned.m8n8.x4.shared.b16 {%0,%1,%2,%3}, [%4];"
        : "=r"(r[0]), "=r"(r[1]), "=r"(r[2]), "=r"(r[3]) : "r"(addr));
}
__device__ __forceinline__ void ldsm_x4_t(uint32_t* r, uint32_t addr) {
    asm volatile("ldmatrix.sync.aligned.m8n8.x4.trans.shared.b16 {%0,%1,%2,%3}, [%4];"
        : "=r"(r[0]), "=r"(r[1]), "=r"(r[2]), "=r"(r[3]) : "r"(addr));
}
__device__ __forceinline__ void mma_bf16(float* c, const uint32_t* a, uint32_t b0, uint32_t b1) {
    asm volatile("mma.sync.aligned.m16n8k16.row.col.f32.bf16.bf16.f32 "
        "{%0,%1,%2,%3}, {%4,%5,%6,%7}, {%8,%9}, {%0,%1,%2,%3};"
        : "+f"(c[0]), "+f"(c[1]), "+f"(c[2]), "+f"(c[3])
        : "r"(a[0]), "r"(a[1]), "r"(a[2]), "r"(a[3]), "r"(b0), "r"(b1));
}

__device__ __forceinline__ void split2(float a, float b, uint32_t& hi, uint32_t& lo) {
    __nv_bfloat162 h = __floats2bfloat162_rn(a, b);
    __nv_bfloat162 l = __floats2bfloat162_rn(
        a - __bfloat162float(__low2bfloat16(h)),
        b - __bfloat162float(__high2bfloat16(h)));
    hi = *reinterpret_cast<uint32_t*>(&h);
    lo = *reinterpret_cast<uint32_t*>(&l);
}

// ---------------- prep kernel: split x and mats into bf16 hi/lo ----------------
#define XBLOCKS 21504   // (2048*10752/4) / 256
#define MBLOCKS 1760    // 450560 / 256

__global__ void prep_kernel(const float* __restrict__ x, MatPtrs mats) {
    const int b = blockIdx.x;
    if (b < XBLOCKS) {
        const size_t i4 = (size_t)b * 256 + threadIdx.x;   // float4 index
        float4 v = reinterpret_cast<const float4*>(x)[i4];
        uint2 uh, ul;
        split2(v.x, v.y, uh.x, ul.x);
        split2(v.z, v.w, uh.y, ul.y);
        reinterpret_cast<uint2*>(g_Xh)[i4] = uh;
        reinterpret_cast<uint2*>(g_Xl)[i4] = ul;
    } else {
        const int idx = (b - XBLOCKS) * 256 + threadIdx.x; // 0..450559
        int g = 0;
        #pragma unroll
        for (int i = 1; i < NGROUPS; i++) if (idx >= c_aoff[i]) g = i;
        const int local = idx - c_aoff[g];
        const int Kp = c_kpad[g], G = c_g[g];
        const int m = local / Kp;
        const int k = local - m * Kp;
        float v = (k < G) ? mats.p[g][m * G + k] : 0.0f;
        __nv_bfloat16 h = __float2bfloat16(v);
        g_Ah[idx] = h;
        g_Al[idx] = __float2bfloat16(v - __bfloat162float(h));
    }
}

// ---------------- main HMMA kernel ----------------
#define APITCH 40    // 32 k + 8 pad bf16 -> 80B rows
#define BPITCH 136   // 128 n + 8 pad bf16 -> 272B rows
#define OFF_AH 0
#define OFF_AL 5120
#define OFF_BH 10240
#define OFF_BL 18944
#define STAGE_BYTES 27648
#define SMEM_TOTAL  (2 * STAGE_BYTES)   // 55296

__global__ __launch_bounds__(256, 2)
void bdiag_hmma_kernel(float* __restrict__ out)
{
    extern __shared__ char smem[];
    const uint32_t sb = smem_u32(smem);

    const int tid    = threadIdx.x;
    const int lane   = tid & 31;
    const int wid    = tid >> 5;
    const int warp_m = wid & 1;
    const int warp_n = wid >> 1;

    const int tile  = blockIdx.y;
    const int grp   = c_tileg[tile];
    const int K     = c_g[grp];
    const int Kpad  = c_kpad[grp];
    const int row0  = c_tiler[tile];
    const int col0  = blockIdx.x * 128;
    const int xbase = c_start[grp];

    const __nv_bfloat16* __restrict__ Ahg = g_Ah + c_aoff[grp];
    const __nv_bfloat16* __restrict__ Alg = g_Al + c_aoff[grp];

    // A-load ownership: thread -> (m, seg)
    const int a_m   = tid >> 2;
    const int a_seg = tid & 3;
    const bool a_ok = (row0 + a_m) < K;

    // Zero-prefill invalid A rows once (both stages, hi+lo); never overwritten.
    if (!a_ok) {
        const uint32_t d = sb + a_m * 80 + a_seg * 16;
        const uint4 z = make_uint4(0, 0, 0, 0);
        *reinterpret_cast<uint4*>(smem + (d - sb) + OFF_AH) = z;
        *reinterpret_cast<uint4*>(smem + (d - sb) + OFF_AL) = z;
        *reinterpret_cast<uint4*>(smem + (d - sb) + STAGE_BYTES + OFF_AH) = z;
        *reinterpret_cast<uint4*>(smem + (d - sb) + STAGE_BYTES + OFF_AL) = z;
    }

    float acc[2][4][4];
    #pragma unroll
    for (int mi = 0; mi < 2; mi++)
        #pragma unroll
        for (int ni = 0; ni < 4; ni++)
            #pragma unroll
            for (int q = 0; q < 4; q++) acc[mi][ni][q] = 0.0f;

    const int lr = lane & 15;
    const int lc = lane >> 4;
    const int nch = Kpad >> 5;

    // ---- cp.async issue for one chunk into one stage
    auto issue = [&](int ch, uint32_t sbuf) {
        const int kc0 = ch << 5;
        if (a_ok) {
            const size_t go = (size_t)(row0 + a_m) * Kpad + kc0 + a_seg * 8;
            const uint32_t d = sbuf + a_m * 80 + a_seg * 16;
            cp16(d + OFF_AH, Ahg + go);
            cp16(d + OFF_AL, Alg + go);
        }
        #pragma unroll
        for (int i = 0; i < 2; i++) {
            const int idx = tid + i * 256;
            const int k   = idx >> 4;
            const int seg = idx & 15;
            const size_t go = (size_t)(xbase + kc0 + k) * NCOLS + col0 + seg * 8;
            const uint32_t d = sbuf + k * 272 + seg * 16;
            cp16(d + OFF_BH, g_Xh + go);
            cp16(d + OFF_BL, g_Xl + go);
        }
    };

    issue(0, sb);
    CP_COMMIT();

    for (int ch = 0; ch < nch; ch++) {
        if (ch + 1 < nch) issue(ch + 1, sb + ((ch + 1) & 1) * STAGE_BYTES);
        CP_COMMIT();
        CP_WAIT1();          // stage ch complete
        __syncthreads();

        const uint32_t sbase = sb + (ch & 1) * STAGE_BYTES;
        #pragma unroll
        for (int ks = 0; ks < 2; ks++) {
            uint32_t ah[2][4], al[2][4];
            #pragma unroll
            for (int mi = 0; mi < 2; mi++) {
                const uint32_t aoff = sbase + OFF_AH +
                    ((warp_m * 32 + mi * 16 + lr) * APITCH + ks * 16 + lc * 8) * 2;
                ldsm_x4(ah[mi], aoff);
                ldsm_x4(al[mi], aoff + (OFF_AL - OFF_AH));
            }
            uint32_t bh[2][4], bl[2][4];
            #pragma unroll
            for (int p = 0; p < 2; p++) {
                const uint32_t boff = sbase + OFF_BH +
                    ((ks * 16 + lr) * BPITCH + warp_n * 32 + p * 16 + lc * 8) * 2;
                ldsm_x4_t(bh[p], boff);
                ldsm_x4_t(bl[p], boff + (OFF_BL - OFF_BH));
            }
            #pragma unroll
            for (int mi = 0; mi < 2; mi++)
                #pragma unroll
                for (int ni = 0; ni < 4; ni++) {
                    const int p = ni >> 1, s = (ni & 1) * 2;
                    mma_bf16(acc[mi][ni], ah[mi], bh[p][s], bh[p][s + 1]);
                    mma_bf16(acc[mi][ni], ah[mi], bl[p][s], bl[p][s + 1]);
                    mma_bf16(acc[mi][ni], al[mi], bh[p][s], bh[p][s + 1]);
                }
        }
        __syncthreads();     // all reads of this stage done before its reuse
    }

    // ---- epilogue: masked float2 stores straight from fragments
    const int rbase = row0 + warp_m * 32 + (lane >> 2);
    const int cb    = col0 + warp_n * 32 + (lane & 3) * 2;
    #pragma unroll
    for (int mi = 0; mi < 2; mi++) {
        #pragma unroll
        for (int half = 0; half < 2; half++) {
            const int row = rbase + mi * 16 + half * 8;
            if (row < K) {
                float* dst = out + (size_t)(xbase + row) * NCOLS + cb;
                #pragma unroll
                for (int ni = 0; ni < 4; ni++)
                    *reinterpret_cast<float2*>(dst + ni * 8) =
                        make_float2(acc[mi][ni][half * 2], acc[mi][ni][half * 2 + 1]);
            }
        }
    }
}

extern "C" void kernel_launch(void* const* d_in, const int* in_sizes, int n_in,
                              void* d_out, int out_size)
{
    const float* x = (const float*)d_in[0];
    float* out = (float*)d_out;

    MatPtrs mats;
    for (int i = 0; i < NGROUPS; i++) mats.p[i] = (const float*)d_in[1 + i];

    cudaFuncSetAttribute(bdiag_hmma_kernel,
                         cudaFuncAttributeMaxDynamicSharedMemorySize, SMEM_TOTAL);

    prep_kernel<<<XBLOCKS + MBLOCKS, 256>>>(x, mats);
    bdiag_hmma_kernel<<<dim3(NCOLS / 128, NTILES), 256, SMEM_TOTAL>>>(out);
}

// round 5
// speedup vs baseline: 1.3538x; 1.3538x over previous
#include <cuda_runtime.h>
#include <cuda_bf16.h>
#include <cstdint>
#include <cstddef>

// Block-diagonal batched GEMM via bf16 HMMA (mma.sync), hi/lo split.
// Round 5: CTA = (group, col-tile). x slab converted ONCE into persistent smem
// (Bh/Bl, full Kpad), then row-tile loop does pure ldmatrix+MMA with A tiles
// streamed via double-buffered cp.async. No x prep kernel.

#define NGROUPS 15
#define NCOLS   10752
#define NCOLT   84

__constant__ int c_g[NGROUPS]     = {64,128,256,96,160,224,192,288,320,112,80,48,32,16,32};
__constant__ int c_start[NGROUPS] = {0,64,192,448,544,704,928,1120,1408,1728,1840,1920,1968,2000,2016};
__constant__ int c_kpad[NGROUPS]  = {64,128,256,128,192,256,192,288,320,128,128,64,64,64,64};
__constant__ int c_aoff[NGROUPS]  = {0,4096,20480,86016,98304,129024,186368,223232,315392,417792,432128,442368,445440,447488,448512};
// group order sorted by work (rowtiles*Kpad) descending, for wave balance
__constant__ int c_order[NGROUPS] = {8,7,2,5,4,6,1,3,9,10,0,11,12,13,14};

// Preconverted block matrices (bf16 hi/lo, K zero-padded). Extra 20480 pad
// elements stay zero-initialized: A loads for masked rows may read there.
__device__ __nv_bfloat16 g_Ah[471040];
__device__ __nv_bfloat16 g_Al[471040];

struct MatPtrs { const float* p[NGROUPS]; };

// ---------------- PTX helpers (compute_103-legal) ----------------
__device__ __forceinline__ uint32_t smem_u32(const void* p) {
    uint32_t a;
    asm("{ .reg .u64 t; cvta.to.shared.u64 t, %1; cvt.u32.u64 %0, t; }" : "=r"(a) : "l"(p));
    return a;
}
__device__ __forceinline__ void cp16(uint32_t dst, const void* src) {
    asm volatile("cp.async.cg.shared.global [%0], [%1], 16;" :: "r"(dst), "l"(src));
}
#define CP_COMMIT() asm volatile("cp.async.commit_group;" ::: "memory")
#define CP_WAIT1()  asm volatile("cp.async.wait_group 1;" ::: "memory")
#define CP_WAIT0()  asm volatile("cp.async.wait_group 0;" ::: "memory")

__device__ __forceinline__ void ldsm_x4(uint32_t* r, uint32_t addr) {
    asm volatile("ldmatrix.sync.aligned.m8n8.x4.shared.b16 {%0,%1,%2,%3}, [%4];"
        : "=r"(r[0]), "=r"(r[1]), "=r"(r[2]), "=r"(r[3]) : "r"(addr));
}
__device__ __forceinline__ void ldsm_x4_t(uint32_t* r, uint32_t addr) {
    asm volatile("ldmatrix.sync.aligned.m8n8.x4.trans.shared.b16 {%0,%1,%2,%3}, [%4];"
        : "=r"(r[0]), "=r"(r[1]), "=r"(r[2]), "=r"(r[3]) : "r"(addr));
}
__device__ __forceinline__ void mma_bf16(float* c, const uint32_t* a, uint32_t b0, uint32_t b1) {
    asm volatile("mma.sync.aligned.m16n8k16.row.col.f32.bf16.bf16.f32 "
        "{%0,%1,%2,%3}, {%4,%5,%6,%7}, {%8,%9}, {%0,%1,%2,%3};"
        : "+f"(c[0]), "+f"(c[1]), "+f"(c[2]), "+f"(c[3])
        : "r"(a[0]), "r"(a[1]), "r"(a[2]), "r"(a[3]), "r"(b0), "r"(b1));
}
__device__ __forceinline__ void split2(float a, float b, uint32_t& hi, uint32_t& lo) {
    __nv_bfloat162 h = __floats2bfloat162_rn(a, b);
    __nv_bfloat162 l = __floats2bfloat162_rn(
        a - __bfloat162float(__low2bfloat16(h)),
        b - __bfloat162float(__high2bfloat16(h)));
    hi = *reinterpret_cast<uint32_t*>(&h);
    lo = *reinterpret_cast<uint32_t*>(&l);
}

// ---------------- prep: split mats into bf16 hi/lo (K zero-padded) ----------------
__global__ void conv_mats_kernel(MatPtrs mats) {
    const int idx = blockIdx.x * 256 + threadIdx.x;   // 0..450559
    if (idx >= 450560) return;
    int g = 0;
    #pragma unroll
    for (int i = 1; i < NGROUPS; i++) if (idx >= c_aoff[i]) g = i;
    const int local = idx - c_aoff[g];
    const int Kp = c_kpad[g], G = c_g[g];
    const int m = local / Kp;
    const int k = local - m * Kp;
    float v = (k < G) ? mats.p[g][m * G + k] : 0.0f;
    __nv_bfloat16 h = __float2bfloat16(v);
    g_Ah[idx] = h;
    g_Al[idx] = __float2bfloat16(v - __bfloat162float(h));
}

// ---------------- smem layout ----------------
#define APITCH 40          // 32 k + 8 pad (bf16)  -> 80B rows
#define BPITCH 136         // 128 n + 8 pad (bf16) -> 272B rows
#define MAXKP  320
#define OFF_BH 0
#define OFF_BL (MAXKP * BPITCH * 2)                 // 87040
#define OFF_A  (2 * MAXKP * BPITCH * 2)             // 174080
#define A_MAT  (128 * APITCH * 2)                   // 10240 bytes per matrix
#define A_STAGE (2 * A_MAT)                          // Ah + Al
#define SMEM_TOTAL (OFF_A + 2 * A_STAGE)            // 215040

__global__ __launch_bounds__(512, 1)
void bdiag_hmma_kernel(const float* __restrict__ x, float* __restrict__ out)
{
    extern __shared__ char smem[];
    const uint32_t sb = smem_u32(smem);

    const int tid    = threadIdx.x;
    const int lane   = tid & 31;
    const int wid    = tid >> 5;
    const int warp_m = wid & 3;    // 4 warps over M (128 rows)
    const int warp_n = wid >> 2;   // 4 warps over N (128 cols)

    const int grp   = c_order[blockIdx.x / NCOLT];
    const int col0  = (blockIdx.x % NCOLT) * 128;
    const int K     = c_g[grp];
    const int Kpad  = c_kpad[grp];
    const int xbase = c_start[grp];
    const int nch   = Kpad >> 5;
    const int nrt   = (K + 127) >> 7;

    const __nv_bfloat16* __restrict__ Ahg = g_Ah + c_aoff[grp];
    const __nv_bfloat16* __restrict__ Alg = g_Al + c_aoff[grp];

    // ---- Phase 1: convert x slab [Kpad x 128] fp32 -> bf16 hi/lo, once.
    __nv_bfloat16* sBh = reinterpret_cast<__nv_bfloat16*>(smem + OFF_BH);
    __nv_bfloat16* sBl = reinterpret_cast<__nv_bfloat16*>(smem + OFF_BL);
    for (int kc = 0; kc < Kpad; kc += 32) {
        #pragma unroll
        for (int i = 0; i < 2; i++) {
            const int idx = tid + i * 512;       // 1024 float4 slots
            const int k   = idx >> 5;
            const int c4  = idx & 31;
            float4 v = make_float4(0.f, 0.f, 0.f, 0.f);
            if (kc + k < K)
                v = *reinterpret_cast<const float4*>(
                        x + (size_t)(xbase + kc + k) * NCOLS + col0 + c4 * 4);
            uint2 uh, ul;
            split2(v.x, v.y, uh.x, ul.x);
            split2(v.z, v.w, uh.y, ul.y);
            *reinterpret_cast<uint2*>(sBh + (kc + k) * BPITCH + c4 * 4) = uh;
            *reinterpret_cast<uint2*>(sBl + (kc + k) * BPITCH + c4 * 4) = ul;
        }
    }
    __syncthreads();

    const int lr = lane & 15;
    const int lc = lane >> 4;

    // A cp.async ownership: 512 threads, one (m, seg) slot each, hi+lo.
    const int a_m   = tid >> 2;
    const int a_seg = tid & 3;

    // ---- Phase 2: row-tile loop, pure HMMA from smem.
    for (int rt = 0; rt < nrt; rt++) {
        const int row0 = rt << 7;

        auto issueA = [&](int ch, int stage) {
            const size_t go = (size_t)(row0 + a_m) * Kpad + (ch << 5) + a_seg * 8;
            const uint32_t d = sb + OFF_A + stage * A_STAGE + a_m * 80 + a_seg * 16;
            cp16(d, Ahg + go);
            cp16(d + A_MAT, Alg + go);
        };

        issueA(0, 0);
        CP_COMMIT();

        float acc[2][4][4];
        #pragma unroll
        for (int mi = 0; mi < 2; mi++)
            #pragma unroll
            for (int ni = 0; ni < 4; ni++)
                #pragma unroll
                for (int q = 0; q < 4; q++) acc[mi][ni][q] = 0.0f;

        for (int ch = 0; ch < nch; ch++) {
            if (ch + 1 < nch) issueA(ch + 1, (ch + 1) & 1);
            CP_COMMIT();
            CP_WAIT1();
            __syncthreads();

            const uint32_t abase = sb + OFF_A + (ch & 1) * A_STAGE;
            const int kc0 = ch << 5;
            #pragma unroll
            for (int ks = 0; ks < 2; ks++) {
                uint32_t ah[2][4], al[2][4];
                #pragma unroll
                for (int mi = 0; mi < 2; mi++) {
                    const uint32_t ao = abase +
                        ((warp_m * 32 + mi * 16 + lr) * APITCH + ks * 16 + lc * 8) * 2;
                    ldsm_x4(ah[mi], ao);
                    ldsm_x4(al[mi], ao + A_MAT);
                }
                uint32_t bh[2][4], bl[2][4];
                #pragma unroll
                for (int p = 0; p < 2; p++) {
                    const uint32_t bo = sb + OFF_BH +
                        ((kc0 + ks * 16 + lr) * BPITCH + warp_n * 32 + p * 16 + lc * 8) * 2;
                    ldsm_x4_t(bh[p], bo);
                    ldsm_x4_t(bl[p], bo + OFF_BL);
                }
                #pragma unroll
                for (int mi = 0; mi < 2; mi++)
                    #pragma unroll
                    for (int ni = 0; ni < 4; ni++) {
                        const int p = ni >> 1, s = (ni & 1) * 2;
                        mma_bf16(acc[mi][ni], ah[mi], bh[p][s], bh[p][s + 1]);
                        mma_bf16(acc[mi][ni], ah[mi], bl[p][s], bl[p][s + 1]);
                        mma_bf16(acc[mi][ni], al[mi], bh[p][s], bh[p][s + 1]);
                    }
            }
            __syncthreads();
        }

        // ---- epilogue for this row-tile: masked float2 stores from fragments
        const int rbase = row0 + warp_m * 32 + (lane >> 2);
        const int cb    = col0 + warp_n * 32 + (lane & 3) * 2;
        #pragma unroll
        for (int mi = 0; mi < 2; mi++) {
            #pragma unroll
            for (int half = 0; half < 2; half++) {
                const int row = rbase + mi * 16 + half * 8;
                if (row < K) {
                    float* dst = out + (size_t)(xbase + row) * NCOLS + cb;
                    #pragma unroll
                    for (int ni = 0; ni < 4; ni++)
                        *reinterpret_cast<float2*>(dst + ni * 8) =
                            make_float2(acc[mi][ni][half * 2], acc[mi][ni][half * 2 + 1]);
                }
            }
        }
        CP_WAIT0();   // drain any stray group before next row-tile reissues
        __syncthreads();
    }
}

extern "C" void kernel_launch(void* const* d_in, const int* in_sizes, int n_in,
                              void* d_out, int out_size)
{
    const float* x = (const float*)d_in[0];
    float* out = (float*)d_out;

    MatPtrs mats;
    for (int i = 0; i < NGROUPS; i++) mats.p[i] = (const float*)d_in[1 + i];

    cudaFuncSetAttribute(bdiag_hmma_kernel,
                         cudaFuncAttributeMaxDynamicSharedMemorySize, SMEM_TOTAL);

    conv_mats_kernel<<<1760, 256>>>(mats);
    bdiag_hmma_kernel<<<NGROUPS * NCOLT, 512, SMEM_TOTAL>>>(x, out);
}

// round 7
// speedup vs baseline: 1.7095x; 1.2627x over previous
#include <cuda_runtime.h>
#include <cuda_bf16.h>
#include <cstdint>
#include <cstddef>

// Block-diagonal batched GEMM via bf16 HMMA (mma.sync), hi/lo split.
// Round 7: R6 with the convB addressing fix (uint2 store = 8 bytes/thread,
// so column offset is c4*8, not c4*16).

#define NGROUPS 15
#define NCOLS   10752
#define NTILES  37

__constant__ int c_g[NGROUPS]     = {64,128,256,96,160,224,192,288,320,112,80,48,32,16,32};
__constant__ int c_start[NGROUPS] = {0,64,192,448,544,704,928,1120,1408,1728,1840,1920,1968,2000,2016};
__constant__ int c_kpad[NGROUPS]  = {64,128,256,128,192,256,192,320,320,128,128,64,64,64,64};
__constant__ int c_aoff[NGROUPS]  = {0,4096,20480,86016,98304,129024,186368,223232,315392,417792,432128,442368,445440,447488,448512};
// tiles sorted heaviest group (most k-chunks) first for wave balance
__constant__ int c_tileg[NTILES]  = {8,8,8,8,8, 7,7,7,7,7, 2,2,2,2, 5,5,5,5,
                                     4,4,4, 6,6,6, 1,1, 3,3, 9,9, 10,10, 0, 11, 12, 13, 14};
__constant__ int c_tiler[NTILES]  = {0,64,128,192,256, 0,64,128,192,256, 0,64,128,192, 0,64,128,192,
                                     0,64,128, 0,64,128, 0,64, 0,64, 0,64, 0,64, 0, 0, 0, 0};

// Preconverted block matrices (bf16 hi/lo, zero K-padding), zero-initialized.
__device__ __nv_bfloat16 g_Ah[450560];
__device__ __nv_bfloat16 g_Al[450560];

struct MatPtrs { const float* p[NGROUPS]; };

// ---------------- PTX helpers (compute_103-legal) ----------------
__device__ __forceinline__ uint32_t smem_u32(const void* p) {
    uint32_t a;
    asm("{ .reg .u64 t; cvta.to.shared.u64 t, %1; cvt.u32.u64 %0, t; }" : "=r"(a) : "l"(p));
    return a;
}
__device__ __forceinline__ void cp16(uint32_t dst, const void* src) {
    asm volatile("cp.async.cg.shared.global [%0], [%1], 16;" :: "r"(dst), "l"(src));
}
#define CP_COMMIT() asm volatile("cp.async.commit_group;" ::: "memory")
#define CP_WAIT1()  asm volatile("cp.async.wait_group 1;" ::: "memory")

__device__ __forceinline__ void ldsm_x4(uint32_t* r, uint32_t addr) {
    asm volatile("ldmatrix.sync.aligned.m8n8.x4.shared.b16 {%0,%1,%2,%3}, [%4];"
        : "=r"(r[0]), "=r"(r[1]), "=r"(r[2]), "=r"(r[3]) : "r"(addr));
}
__device__ __forceinline__ void ldsm_x4_t(uint32_t* r, uint32_t addr) {
    asm volatile("ldmatrix.sync.aligned.m8n8.x4.trans.shared.b16 {%0,%1,%2,%3}, [%4];"
        : "=r"(r[0]), "=r"(r[1]), "=r"(r[2]), "=r"(r[3]) : "r"(addr));
}
__device__ __forceinline__ void mma_bf16(float* c, const uint32_t* a, uint32_t b0, uint32_t b1) {
    asm volatile("mma.sync.aligned.m16n8k16.row.col.f32.bf16.bf16.f32 "
        "{%0,%1,%2,%3}, {%4,%5,%6,%7}, {%8,%9}, {%0,%1,%2,%3};"
        : "+f"(c[0]), "+f"(c[1]), "+f"(c[2]), "+f"(c[3])
        : "r"(a[0]), "r"(a[1]), "r"(a[2]), "r"(a[3]), "r"(b0), "r"(b1));
}
__device__ __forceinline__ void split2(float a, float b, uint32_t& hi, uint32_t& lo) {
    __nv_bfloat162 h = __floats2bfloat162_rn(a, b);
    __nv_bfloat162 l = __floats2bfloat162_rn(
        a - __bfloat162float(__low2bfloat16(h)),
        b - __bfloat162float(__high2bfloat16(h)));
    hi = *reinterpret_cast<uint32_t*>(&h);
    lo = *reinterpret_cast<uint32_t*>(&l);
}

// ---------------- prep: split mats into bf16 hi/lo (K zero-padded) ----------------
__global__ void conv_mats_kernel(MatPtrs mats) {
    const int idx = blockIdx.x * 256 + threadIdx.x;
    if (idx >= 450560) return;
    int g = 0;
    #pragma unroll
    for (int i = 1; i < NGROUPS; i++) if (idx >= c_aoff[i]) g = i;
    const int local = idx - c_aoff[g];
    const int Kp = c_kpad[g], G = c_g[g];
    const int m = local / Kp;
    const int k = local - m * Kp;
    float v = (k < G) ? mats.p[g][m * G + k] : 0.0f;
    __nv_bfloat16 h = __float2bfloat16(v);
    g_Ah[idx] = h;
    g_Al[idx] = __float2bfloat16(v - __bfloat162float(h));
}

// ---------------- main HMMA kernel ----------------
#define APITCH 40    // 32 k + 8 pad bf16 -> 80B rows
#define BPITCH 136   // 128 n + 8 pad bf16 -> 272B rows
#define OFF_AH 0
#define OFF_AL 5120
#define OFF_BH 10240
#define OFF_BL 18944
#define STAGE_BYTES 27648
#define SMEM_TOTAL  (2 * STAGE_BYTES)   // 55296 -> 2 CTAs/SM

__global__ __launch_bounds__(256, 2)
void bdiag_hmma_kernel(const float* __restrict__ x, float* __restrict__ out)
{
    extern __shared__ char smem[];
    const uint32_t sb = smem_u32(smem);

    const int tid    = threadIdx.x;
    const int lane   = tid & 31;
    const int wid    = tid >> 5;
    const int warp_m = wid & 1;
    const int warp_n = wid >> 1;

    const int tile  = blockIdx.y;
    const int grp   = c_tileg[tile];
    const int K     = c_g[grp];
    const int Kpad  = c_kpad[grp];
    const int row0  = c_tiler[tile];
    const int col0  = blockIdx.x * 128;
    const int xbase = c_start[grp];

    const __nv_bfloat16* __restrict__ Ahg = g_Ah + c_aoff[grp];
    const __nv_bfloat16* __restrict__ Alg = g_Al + c_aoff[grp];

    // A cp.async ownership
    const int a_m   = tid >> 2;
    const int a_seg = tid & 3;
    const bool a_ok = (row0 + a_m) < K;

    // Zero-prefill invalid A rows once (both stages, hi+lo); never overwritten.
    if (!a_ok) {
        const uint32_t d = a_m * 80 + a_seg * 16;
        const uint4 z = make_uint4(0, 0, 0, 0);
        *reinterpret_cast<uint4*>(smem + d + OFF_AH) = z;
        *reinterpret_cast<uint4*>(smem + d + OFF_AL) = z;
        *reinterpret_cast<uint4*>(smem + d + STAGE_BYTES + OFF_AH) = z;
        *reinterpret_cast<uint4*>(smem + d + STAGE_BYTES + OFF_AL) = z;
    }

    // B ownership: 4 float4 per thread; slot idx = tid + j*256
    const int b_k[4]  = { tid >> 5, (tid + 256) >> 5, (tid + 512) >> 5, (tid + 768) >> 5 };
    const int b_c4    = tid & 31;   // same low 5 bits for all j
    const int nch     = Kpad >> 5;

    auto issueA = [&](int ch, uint32_t sbuf) {
        if (a_ok) {
            const size_t go = (size_t)(row0 + a_m) * Kpad + (ch << 5) + a_seg * 8;
            const uint32_t d = sbuf + a_m * 80 + a_seg * 16;
            cp16(d + OFF_AH, Ahg + go);
            cp16(d + OFF_AL, Alg + go);
        }
    };
    float4 r[4];
    auto ldgB = [&](int ch) {
        const int kc0 = ch << 5;
        #pragma unroll
        for (int j = 0; j < 4; j++) {
            r[j] = make_float4(0.f, 0.f, 0.f, 0.f);
            if (kc0 + b_k[j] < K)
                r[j] = *reinterpret_cast<const float4*>(
                    x + (size_t)(xbase + kc0 + b_k[j]) * NCOLS + col0 + b_c4 * 4);
        }
    };
    auto convB = [&](uint32_t sbuf) {
        #pragma unroll
        for (int j = 0; j < 4; j++) {
            uint2 uh, ul;
            split2(r[j].x, r[j].y, uh.x, ul.x);
            split2(r[j].z, r[j].w, uh.y, ul.y);
            // 4 bf16 = 8 bytes per thread-slot: column byte offset = b_c4 * 8
            const uint32_t d = (sbuf - sb) + b_k[j] * 272 + b_c4 * 8;
            *reinterpret_cast<uint2*>(smem + d + OFF_BH) = uh;
            *reinterpret_cast<uint2*>(smem + d + OFF_BL) = ul;
        }
    };

    float acc[2][4][4];
    #pragma unroll
    for (int mi = 0; mi < 2; mi++)
        #pragma unroll
        for (int ni = 0; ni < 4; ni++)
            #pragma unroll
            for (int q = 0; q < 4; q++) acc[mi][ni][q] = 0.0f;

    const int lr = lane & 15;
    const int lc = lane >> 4;

    // ---- prologue: chunk 0 staged, chunk 1 fp32 in regs
    ldgB(0);
    issueA(0, sb);
    CP_COMMIT();
    convB(sb);               // stage 0 B (stalls once on LDG)
    if (nch > 1) ldgB(1);

    for (int ch = 0; ch < nch; ch++) {
        if (ch + 1 < nch) issueA(ch + 1, sb + ((ch + 1) & 1) * STAGE_BYTES);
        CP_COMMIT();
        CP_WAIT1();          // A(ch) landed (groups complete in order)
        __syncthreads();     // stage ch fully visible to all warps

        const uint32_t sbase = sb + (ch & 1) * STAGE_BYTES;
        #pragma unroll
        for (int ks = 0; ks < 2; ks++) {
            uint32_t ah[2][4], al[2][4];
            #pragma unroll
            for (int mi = 0; mi < 2; mi++) {
                const uint32_t ao = sbase + OFF_AH +
                    ((warp_m * 32 + mi * 16 + lr) * APITCH + ks * 16 + lc * 8) * 2;
                ldsm_x4(ah[mi], ao);
                ldsm_x4(al[mi], ao + (OFF_AL - OFF_AH));
            }
            uint32_t bh[2][4], bl[2][4];
            #pragma unroll
            for (int p = 0; p < 2; p++) {
                const uint32_t bo = sbase + OFF_BH +
                    ((ks * 16 + lr) * BPITCH + warp_n * 32 + p * 16 + lc * 8) * 2;
                ldsm_x4_t(bh[p], bo);
                ldsm_x4_t(bl[p], bo + (OFF_BL - OFF_BH));
            }
            #pragma unroll
            for (int mi = 0; mi < 2; mi++)
                #pragma unroll
                for (int ni = 0; ni < 4; ni++) {
                    const int p = ni >> 1, s = (ni & 1) * 2;
                    mma_bf16(acc[mi][ni], ah[mi], bh[p][s], bh[p][s + 1]);
                    mma_bf16(acc[mi][ni], ah[mi], bl[p][s], bl[p][s + 1]);
                    mma_bf16(acc[mi][ni], al[mi], bh[p][s], bh[p][s + 1]);
                }
        }

        // convert next chunk's B (regs -> other stage), then refill regs
        if (ch + 1 < nch) convB(sb + ((ch + 1) & 1) * STAGE_BYTES);
        if (ch + 2 < nch) ldgB(ch + 2);

        __syncthreads();     // stage reads done + next-stage B STS ordered
    }

    // ---- epilogue: masked float2 stores straight from fragments
    const int rbase = row0 + warp_m * 32 + (lane >> 2);
    const int cb    = col0 + warp_n * 32 + (lane & 3) * 2;
    #pragma unroll
    for (int mi = 0; mi < 2; mi++) {
        #pragma unroll
        for (int half = 0; half < 2; half++) {
            const int row = rbase + mi * 16 + half * 8;
            if (row < K) {
                float* dst = out + (size_t)(xbase + row) * NCOLS + cb;
                #pragma unroll
                for (int ni = 0; ni < 4; ni++)
                    *reinterpret_cast<float2*>(dst + ni * 8) =
                        make_float2(acc[mi][ni][half * 2], acc[mi][ni][half * 2 + 1]);
            }
        }
    }
}

extern "C" void kernel_launch(void* const* d_in, const int* in_sizes, int n_in,
                              void* d_out, int out_size)
{
    const float* x = (const float*)d_in[0];
    float* out = (float*)d_out;

    MatPtrs mats;
    for (int i = 0; i < NGROUPS; i++) mats.p[i] = (const float*)d_in[1 + i];

    cudaFuncSetAttribute(bdiag_hmma_kernel,
                         cudaFuncAttributeMaxDynamicSharedMemorySize, SMEM_TOTAL);

    conv_mats_kernel<<<1760, 256>>>(mats);
    bdiag_hmma_kernel<<<dim3(NCOLS / 128, NTILES), 256, SMEM_TOTAL>>>(x, out);
}